// round 1
// baseline (speedup 1.0000x reference)
#include <cuda_runtime.h>
#include <cuda_bf16.h>
#include <cstdint>

// Problem constants
#define K_DIM 4096
#define N_DIM 4096

#define BM 128
#define BN 128
#define BK 32
#define LDT 40                 // padded smem row stride in bf16 (80B -> conflict-free ldmatrix)
#define TILE (128 * LDT)       // elements per smem array per stage
#define THREADS 256

// Scratch: split bf16 operands (device globals are the sanctioned scratch path)
__device__ __nv_bfloat16 g_xhi[8192L * K_DIM];
__device__ __nv_bfloat16 g_xlo[8192L * K_DIM];
__device__ __nv_bfloat16 g_whi[(long)N_DIM * K_DIM];
__device__ __nv_bfloat16 g_wlo[(long)N_DIM * K_DIM];

// ---------------------------------------------------------------------------
// Prep kernels
// ---------------------------------------------------------------------------
__device__ __forceinline__ void split1(float v, __nv_bfloat16& h, __nv_bfloat16& l) {
    h = __float2bfloat16(v);
    l = __float2bfloat16(v - __bfloat162float(h));
}

__global__ void k_split_x(const float* __restrict__ x, long n4) {
    long i = (long)blockIdx.x * blockDim.x + threadIdx.x;
    if (i >= n4) return;
    float4 v = reinterpret_cast<const float4*>(x)[i];
    __nv_bfloat16 h0, h1, h2, h3, l0, l1, l2, l3;
    split1(v.x, h0, l0); split1(v.y, h1, l1);
    split1(v.z, h2, l2); split1(v.w, h3, l3);
    __nv_bfloat162* hi2 = reinterpret_cast<__nv_bfloat162*>(g_xhi);
    __nv_bfloat162* lo2 = reinterpret_cast<__nv_bfloat162*>(g_xlo);
    hi2[2 * i]     = __halves2bfloat162(h0, h1);
    hi2[2 * i + 1] = __halves2bfloat162(h2, h3);
    lo2[2 * i]     = __halves2bfloat162(l0, l1);
    lo2[2 * i + 1] = __halves2bfloat162(l2, l3);
}

__global__ void k_dequant_w(const float* __restrict__ wq,
                            const float* __restrict__ scales, long n4) {
    long i = (long)blockIdx.x * blockDim.x + threadIdx.x;
    if (i >= n4) return;
    float s = scales[(4 * i) >> 7];  // 128-element blocks; 4 elems never straddle
    float4 v = reinterpret_cast<const float4*>(wq)[i];
    __nv_bfloat16 h0, h1, h2, h3, l0, l1, l2, l3;
    split1(v.x * s, h0, l0); split1(v.y * s, h1, l1);
    split1(v.z * s, h2, l2); split1(v.w * s, h3, l3);
    __nv_bfloat162* hi2 = reinterpret_cast<__nv_bfloat162*>(g_whi);
    __nv_bfloat162* lo2 = reinterpret_cast<__nv_bfloat162*>(g_wlo);
    hi2[2 * i]     = __halves2bfloat162(h0, h1);
    hi2[2 * i + 1] = __halves2bfloat162(h2, h3);
    lo2[2 * i]     = __halves2bfloat162(l0, l1);
    lo2[2 * i + 1] = __halves2bfloat162(l2, l3);
}

// ---------------------------------------------------------------------------
// GEMM
// ---------------------------------------------------------------------------
__device__ __forceinline__ void cp16(uint32_t smem_addr, const void* gptr) {
    asm volatile("cp.async.cg.shared.global [%0], [%1], 16;" ::"r"(smem_addr), "l"(gptr));
}
__device__ __forceinline__ void cp_commit() { asm volatile("cp.async.commit_group;"); }
__device__ __forceinline__ void cp_wait0() { asm volatile("cp.async.wait_group 0;"); }

__device__ __forceinline__ void ldsm4(uint32_t* r, uint32_t addr) {
    asm volatile("ldmatrix.sync.aligned.m8n8.x4.shared.b16 {%0,%1,%2,%3}, [%4];"
                 : "=r"(r[0]), "=r"(r[1]), "=r"(r[2]), "=r"(r[3]) : "r"(addr));
}
__device__ __forceinline__ void ldsm2(uint32_t* r, uint32_t addr) {
    asm volatile("ldmatrix.sync.aligned.m8n8.x2.shared.b16 {%0,%1}, [%2];"
                 : "=r"(r[0]), "=r"(r[1]) : "r"(addr));
}
__device__ __forceinline__ void mma_bf16(float* c, const uint32_t* a, const uint32_t* b) {
    asm volatile(
        "mma.sync.aligned.m16n8k16.row.col.f32.bf16.bf16.f32 "
        "{%0,%1,%2,%3}, {%4,%5,%6,%7}, {%8,%9}, {%0,%1,%2,%3};"
        : "+f"(c[0]), "+f"(c[1]), "+f"(c[2]), "+f"(c[3])
        : "r"(a[0]), "r"(a[1]), "r"(a[2]), "r"(a[3]), "r"(b[0]), "r"(b[1]));
}

__global__ __launch_bounds__(THREADS, 1)
void k_gemm_split(const float* __restrict__ bias, float* __restrict__ out) {
    extern __shared__ __nv_bfloat16 sm[];
    const int tid  = threadIdx.x;
    const int lane = tid & 31;
    const int warp = tid >> 5;
    const long m0 = (long)blockIdx.y * BM;
    const long n0 = (long)blockIdx.x * BN;
    const int wm = (warp & 1) * 64;   // warp M offset in CTA tile
    const int wn = (warp >> 1) * 32;  // warp N offset

    const uint32_t sbase = (uint32_t)__cvta_generic_to_shared(sm);

    // Global->smem vector mapping: v = tid (+256); row = v>>2, col = (v&3)*8
    const int vr = tid >> 2;
    const int vc = (tid & 3) * 8;

    float c[4][4][4];
#pragma unroll
    for (int mi = 0; mi < 4; ++mi)
#pragma unroll
        for (int ni = 0; ni < 4; ++ni)
#pragma unroll
            for (int j = 0; j < 4; ++j) c[mi][ni][j] = 0.f;

    auto stage_off = [](int s, int arr) { return (uint32_t)((s * 4 + arr) * TILE); };

    auto issue = [&](int kt, int st) {
        const int kc = kt * BK + vc;
#pragma unroll
        for (int h = 0; h < 2; ++h) {
            const int r = vr + h * 64;
            const uint32_t d = (uint32_t)(r * LDT + vc);
            cp16(sbase + (stage_off(st, 0) + d) * 2, g_xhi + (m0 + r) * K_DIM + kc);
            cp16(sbase + (stage_off(st, 1) + d) * 2, g_xlo + (m0 + r) * K_DIM + kc);
            cp16(sbase + (stage_off(st, 2) + d) * 2, g_whi + (n0 + r) * (long)K_DIM + kc);
            cp16(sbase + (stage_off(st, 3) + d) * 2, g_wlo + (n0 + r) * (long)K_DIM + kc);
        }
    };

    const int KT = K_DIM / BK;
    int s = 0;
    issue(0, 0);
    cp_commit();

    for (int kt = 0; kt < KT; ++kt) {
        cp_wait0();
        __syncthreads();
        if (kt + 1 < KT) { issue(kt + 1, s ^ 1); cp_commit(); }

#pragma unroll
        for (int kk = 0; kk < 2; ++kk) {
            uint32_t ah[4][4], al[4][4], bh[4][2], bl[4][2];
            const uint32_t a_row = (uint32_t)(wm + (lane & 15));
            const uint32_t a_col = (uint32_t)(kk * 16 + (lane >> 4) * 8);
#pragma unroll
            for (int mi = 0; mi < 4; ++mi) {
                uint32_t off = (a_row + mi * 16) * LDT + a_col;
                ldsm4(ah[mi], sbase + (stage_off(s, 0) + off) * 2);
                ldsm4(al[mi], sbase + (stage_off(s, 1) + off) * 2);
            }
            const uint32_t b_row = (uint32_t)(wn + (lane & 7));
            const uint32_t b_col = (uint32_t)(kk * 16 + ((lane >> 3) & 1) * 8);
#pragma unroll
            for (int ni = 0; ni < 4; ++ni) {
                uint32_t off = (b_row + ni * 8) * LDT + b_col;
                ldsm2(bh[ni], sbase + (stage_off(s, 2) + off) * 2);
                ldsm2(bl[ni], sbase + (stage_off(s, 3) + off) * 2);
            }
#pragma unroll
            for (int mi = 0; mi < 4; ++mi)
#pragma unroll
                for (int ni = 0; ni < 4; ++ni) {
                    mma_bf16(c[mi][ni], ah[mi], bh[ni]);  // hi*hi
                    mma_bf16(c[mi][ni], ah[mi], bl[ni]);  // hi*lo
                    mma_bf16(c[mi][ni], al[mi], bh[ni]);  // lo*hi
                }
        }
        s ^= 1;
    }

    // Epilogue: y += bias
    const int qr = lane >> 2;
    const int qc = (lane & 3) * 2;
#pragma unroll
    for (int mi = 0; mi < 4; ++mi) {
        const long gm = m0 + wm + mi * 16 + qr;
        float* o0 = out + gm * N_DIM + n0 + wn;
        float* o1 = o0 + 8L * N_DIM;
#pragma unroll
        for (int ni = 0; ni < 4; ++ni) {
            const int col = (int)(n0 + wn) + ni * 8 + qc;
            const float b0 = __ldg(bias + col);
            const float b1 = __ldg(bias + col + 1);
            float2 v0 = make_float2(c[mi][ni][0] + b0, c[mi][ni][1] + b1);
            float2 v1 = make_float2(c[mi][ni][2] + b0, c[mi][ni][3] + b1);
            *reinterpret_cast<float2*>(o0 + ni * 8 + qc) = v0;
            *reinterpret_cast<float2*>(o1 + ni * 8 + qc) = v1;
        }
    }
}

// ---------------------------------------------------------------------------
// Launch
// ---------------------------------------------------------------------------
extern "C" void kernel_launch(void* const* d_in, const int* in_sizes, int n_in,
                              void* d_out, int out_size) {
    const float* x      = (const float*)d_in[0];
    const float* wq     = (const float*)d_in[1];
    const float* scales = (const float*)d_in[2];
    const float* bias   = (const float*)d_in[3];
    float* out = (float*)d_out;

    const long n_x = in_sizes[0];            // M*K
    const long M   = n_x / K_DIM;            // 8192
    const long n_w = (long)N_DIM * K_DIM;

    // prep: split x and dequant+split w
    {
        long n4 = n_x / 4;
        int grid = (int)((n4 + 255) / 256);
        k_split_x<<<grid, 256>>>(x, n4);
    }
    {
        long n4 = n_w / 4;
        int grid = (int)((n4 + 255) / 256);
        k_dequant_w<<<grid, 256>>>(wq, scales, n4);
    }

    // GEMM
    const int smem_bytes = 8 * TILE * 2;  // 4 arrays x 2 stages
    cudaFuncSetAttribute(k_gemm_split, cudaFuncAttributeMaxDynamicSharedMemorySize, smem_bytes);
    dim3 grid(N_DIM / BN, (unsigned)(M / BM));
    k_gemm_split<<<grid, THREADS, smem_bytes>>>(bias, out);
}

// round 4
// speedup vs baseline: 1.4920x; 1.4920x over previous
#include <cuda_runtime.h>
#include <cuda_fp16.h>
#include <cstdint>

// Problem constants
#define K_DIM 4096
#define N_DIM 4096
#define M_DIM 8192

// GEMM tiling
#define BM 128
#define BN 128
#define BK 64
#define STAGES 3
#define THREADS 256

// smem layout
#define ROWB 144                    // 64 halves (128B) + 16B pad -> conflict-free ldsm
#define ARR_B (128 * ROWB)          // 18432 B per operand tile
#define STG_B (3 * ARR_B)           // xh, xl, w tiles per stage
#define SM_SCALES 0                 // 4096 floats, transposed [kb][n]
#define SM_TILES 16384
#define SMEM_TOTAL (SM_TILES + STAGES * STG_B)   // 182272 B

// Scratch: fp16 operands. W is fp8-valued -> EXACT in fp16 (no scale folded).
__device__ __half g_xh[(long)M_DIM * K_DIM];
__device__ __half g_xl[(long)M_DIM * K_DIM];
__device__ __half g_wh[(long)N_DIM * K_DIM];

// ---------------------------------------------------------------------------
// Prep kernels
// ---------------------------------------------------------------------------
__global__ void k_prep_x(const float* __restrict__ x, long n4) {
    long i = (long)blockIdx.x * blockDim.x + threadIdx.x;
    if (i >= n4) return;
    float4 v = reinterpret_cast<const float4*>(x)[i];
    __half h0 = __float2half_rn(v.x), h1 = __float2half_rn(v.y);
    __half h2 = __float2half_rn(v.z), h3 = __float2half_rn(v.w);
    __half l0 = __float2half_rn(v.x - __half2float(h0));
    __half l1 = __float2half_rn(v.y - __half2float(h1));
    __half l2 = __float2half_rn(v.z - __half2float(h2));
    __half l3 = __float2half_rn(v.w - __half2float(h3));
    __half2* hi2 = reinterpret_cast<__half2*>(g_xh);
    __half2* lo2 = reinterpret_cast<__half2*>(g_xl);
    hi2[2 * i]     = __halves2half2(h0, h1);
    hi2[2 * i + 1] = __halves2half2(h2, h3);
    lo2[2 * i]     = __halves2half2(l0, l1);
    lo2[2 * i + 1] = __halves2half2(l2, l3);
}

__global__ void k_prep_w(const float* __restrict__ wq, long n4) {
    long i = (long)blockIdx.x * blockDim.x + threadIdx.x;
    if (i >= n4) return;
    float4 v = reinterpret_cast<const float4*>(wq)[i];
    __half2* w2 = reinterpret_cast<__half2*>(g_wh);
    w2[2 * i]     = __halves2half2(__float2half_rn(v.x), __float2half_rn(v.y));
    w2[2 * i + 1] = __halves2half2(__float2half_rn(v.z), __float2half_rn(v.w));
}

// ---------------------------------------------------------------------------
// MMA helpers
// ---------------------------------------------------------------------------
__device__ __forceinline__ void cp16(uint32_t saddr, const void* g) {
    asm volatile("cp.async.cg.shared.global [%0], [%1], 16;" ::"r"(saddr), "l"(g));
}
__device__ __forceinline__ void ldsm4(uint32_t* r, uint32_t addr) {
    asm volatile("ldmatrix.sync.aligned.m8n8.x4.shared.b16 {%0,%1,%2,%3}, [%4];"
                 : "=r"(r[0]), "=r"(r[1]), "=r"(r[2]), "=r"(r[3]) : "r"(addr));
}
__device__ __forceinline__ void ldsm2(uint32_t* r, uint32_t addr) {
    asm volatile("ldmatrix.sync.aligned.m8n8.x2.shared.b16 {%0,%1}, [%2];"
                 : "=r"(r[0]), "=r"(r[1]) : "r"(addr));
}
__device__ __forceinline__ void mma_f16(float* c, const uint32_t* a, const uint32_t* b) {
    asm volatile(
        "mma.sync.aligned.m16n8k16.row.col.f32.f16.f16.f32 "
        "{%0,%1,%2,%3}, {%4,%5,%6,%7}, {%8,%9}, {%0,%1,%2,%3};"
        : "+f"(c[0]), "+f"(c[1]), "+f"(c[2]), "+f"(c[3])
        : "r"(a[0]), "r"(a[1]), "r"(a[2]), "r"(a[3]), "r"(b[0]), "r"(b[1]));
}

// ---------------------------------------------------------------------------
// GEMM: out[M,N] = (Xh + Xl) @ Wq^T with per-128-block fp32 scaling + bias
// ---------------------------------------------------------------------------
__global__ __launch_bounds__(THREADS, 1)
void k_gemm(const float* __restrict__ scales, const float* __restrict__ bias,
            float* __restrict__ out) {
    extern __shared__ char smc[];
    float* sscale = reinterpret_cast<float*>(smc);
    const uint32_t sbase = (uint32_t)__cvta_generic_to_shared(smc);
    const int tid  = threadIdx.x;
    const int lane = tid & 31;
    const int warp = tid >> 5;
    const long m0 = (long)blockIdx.y * BM;
    const long n0 = (long)blockIdx.x * BN;
    const int wm = (warp & 1) * 64;
    const int wn = (warp >> 1) * 32;

    // Preload scale tile transposed: sscale[kb*128 + n] = scales[(n0+n)*32 + kb]
#pragma unroll
    for (int i = tid; i < BN * 32; i += THREADS) {
        const int n = i >> 5, kb = i & 31;
        sscale[kb * 128 + n] = scales[(n0 + n) * 32 + kb];
    }

    float c[4][4][4], p[4][4][4];
#pragma unroll
    for (int mi = 0; mi < 4; ++mi)
#pragma unroll
        for (int ni = 0; ni < 4; ++ni)
#pragma unroll
            for (int j = 0; j < 4; ++j) { c[mi][ni][j] = 0.f; p[mi][ni][j] = 0.f; }

    // cp.async loader: thread t handles chunks c = t + i*256; row=c>>3, ch=c&7
    auto load_stage = [&](int kt, int s) {
        const uint32_t st = sbase + SM_TILES + s * STG_B;
        const int kc0 = kt * BK;
#pragma unroll
        for (int i = 0; i < 4; ++i) {
            const int cch = tid + i * THREADS;
            const int row = cch >> 3;
            const int ch  = cch & 7;
            const uint32_t off = (uint32_t)(row * ROWB + ch * 16);
            const long gx = (m0 + row) * K_DIM + kc0 + ch * 8;
            const long gw = (n0 + row) * (long)K_DIM + kc0 + ch * 8;
            cp16(st + off, g_xh + gx);
            cp16(st + ARR_B + off, g_xl + gx);
            cp16(st + 2 * ARR_B + off, g_wh + gw);
        }
        asm volatile("cp.async.commit_group;");
    };

    const int KT = K_DIM / BK;   // 64
    load_stage(0, 0);
    load_stage(1, 1);

    const int qr = lane >> 2;
    const int qc = (lane & 3) * 2;
    const uint32_t a_rowoff = (uint32_t)(wm + (lane & 15));
    const uint32_t a_cb     = (uint32_t)((lane >> 4) * 16);
    const uint32_t b_rowoff = (uint32_t)(wn + (lane & 7));
    const uint32_t b_cb     = (uint32_t)(((lane >> 3) & 1) * 16);

    for (int kt = 0; kt < KT; ++kt) {
        const int s = kt % STAGES;
        asm volatile("cp.async.wait_group %0;" :: "n"(STAGES - 2));
        __syncthreads();
        if (kt + 2 < KT) load_stage(kt + 2, (kt + 2) % STAGES);

        const uint32_t st = sbase + SM_TILES + s * STG_B;
#pragma unroll
        for (int kk = 0; kk < 4; ++kk) {
            uint32_t ah[4][4], al[4][4], bf[4][2];
#pragma unroll
            for (int mi = 0; mi < 4; ++mi) {
                const uint32_t off = (a_rowoff + mi * 16) * ROWB + kk * 32 + a_cb;
                ldsm4(ah[mi], st + off);
                ldsm4(al[mi], st + ARR_B + off);
            }
#pragma unroll
            for (int ni = 0; ni < 4; ++ni) {
                const uint32_t off = (b_rowoff + ni * 8) * ROWB + kk * 32 + b_cb;
                ldsm2(bf[ni], st + 2 * ARR_B + off);
            }
#pragma unroll
            for (int mi = 0; mi < 4; ++mi)
#pragma unroll
                for (int ni = 0; ni < 4; ++ni) {
                    mma_f16(p[mi][ni], ah[mi], bf[ni]);
                    mma_f16(p[mi][ni], al[mi], bf[ni]);
                }
        }

        // Every 2 BK iters = one 128-elem scale block: C += s * part
        if (kt & 1) {
            const int kb = kt >> 1;
            const float* sk = sscale + kb * 128;
#pragma unroll
            for (int ni = 0; ni < 4; ++ni) {
                const int col = wn + ni * 8 + qc;
                const float s0 = sk[col];
                const float s1 = sk[col + 1];
#pragma unroll
                for (int mi = 0; mi < 4; ++mi) {
                    c[mi][ni][0] += s0 * p[mi][ni][0];
                    c[mi][ni][1] += s1 * p[mi][ni][1];
                    c[mi][ni][2] += s0 * p[mi][ni][2];
                    c[mi][ni][3] += s1 * p[mi][ni][3];
                    p[mi][ni][0] = 0.f; p[mi][ni][1] = 0.f;
                    p[mi][ni][2] = 0.f; p[mi][ni][3] = 0.f;
                }
            }
        }
    }

    // Epilogue: y += bias, store
#pragma unroll
    for (int mi = 0; mi < 4; ++mi) {
        const long gm = m0 + wm + mi * 16 + qr;
        float* o0 = out + gm * N_DIM + n0 + wn;
        float* o1 = o0 + 8L * N_DIM;
#pragma unroll
        for (int ni = 0; ni < 4; ++ni) {
            const int col = (int)n0 + wn + ni * 8 + qc;
            const float b0 = __ldg(bias + col);
            const float b1 = __ldg(bias + col + 1);
            float2 v0 = make_float2(c[mi][ni][0] + b0, c[mi][ni][1] + b1);
            float2 v1 = make_float2(c[mi][ni][2] + b0, c[mi][ni][3] + b1);
            *reinterpret_cast<float2*>(o0 + ni * 8 + qc) = v0;
            *reinterpret_cast<float2*>(o1 + ni * 8 + qc) = v1;
        }
    }
}

// ---------------------------------------------------------------------------
// Launch
// ---------------------------------------------------------------------------
extern "C" void kernel_launch(void* const* d_in, const int* in_sizes, int n_in,
                              void* d_out, int out_size) {
    const float* x      = (const float*)d_in[0];
    const float* wq     = (const float*)d_in[1];
    const float* scales = (const float*)d_in[2];
    const float* bias   = (const float*)d_in[3];
    float* out = (float*)d_out;

    const long n_x = in_sizes[0];           // M*K
    const long M   = n_x / K_DIM;           // 8192
    const long n_w = (long)N_DIM * K_DIM;

    {
        long n4 = n_x / 4;
        k_prep_x<<<(int)((n4 + 255) / 256), 256>>>(x, n4);
    }
    {
        long n4 = n_w / 4;
        k_prep_w<<<(int)((n4 + 255) / 256), 256>>>(wq, n4);
    }

    cudaFuncSetAttribute(k_gemm, cudaFuncAttributeMaxDynamicSharedMemorySize,
                         SMEM_TOTAL);
    dim3 grid(N_DIM / BN, (unsigned)(M / BM));
    k_gemm<<<grid, THREADS, SMEM_TOTAL>>>(scales, bias, out);
}

// round 5
// speedup vs baseline: 2.3762x; 1.5926x over previous
#include <cuda_runtime.h>
#include <cuda_fp16.h>
#include <cstdint>

// Problem constants
#define K_DIM 4096
#define N_DIM 4096
#define M_DIM 8192

// GEMM tiling
#define BM 128
#define BN 128
#define BK 64
#define STAGES 4
#define THREADS 256

// smem layout
#define ROWB 144                    // 64 halves (128B) + 16B pad -> conflict-free ldsm
#define ARR_B (128 * ROWB)          // 18432 B per operand tile
#define STG_B (2 * ARR_B)           // xh, w tiles per stage
#define SM_TILES 16384              // scales live in [0, 16384)
#define SMEM_TOTAL (SM_TILES + STAGES * STG_B)   // 163840 B

// Scratch: fp16 operands. W is fp8-valued -> EXACT in fp16 (no scale folded).
__device__ __half g_xh[(long)M_DIM * K_DIM];
__device__ __half g_wh[(long)N_DIM * K_DIM];

// ---------------------------------------------------------------------------
// Prep kernels
// ---------------------------------------------------------------------------
__global__ void k_prep_x(const float* __restrict__ x, long n4) {
    long i = (long)blockIdx.x * blockDim.x + threadIdx.x;
    if (i >= n4) return;
    float4 v = reinterpret_cast<const float4*>(x)[i];
    __half2* hi2 = reinterpret_cast<__half2*>(g_xh);
    hi2[2 * i]     = __halves2half2(__float2half_rn(v.x), __float2half_rn(v.y));
    hi2[2 * i + 1] = __halves2half2(__float2half_rn(v.z), __float2half_rn(v.w));
}

__global__ void k_prep_w(const float* __restrict__ wq, long n4) {
    long i = (long)blockIdx.x * blockDim.x + threadIdx.x;
    if (i >= n4) return;
    float4 v = reinterpret_cast<const float4*>(wq)[i];
    __half2* w2 = reinterpret_cast<__half2*>(g_wh);
    w2[2 * i]     = __halves2half2(__float2half_rn(v.x), __float2half_rn(v.y));
    w2[2 * i + 1] = __halves2half2(__float2half_rn(v.z), __float2half_rn(v.w));
}

// ---------------------------------------------------------------------------
// MMA helpers
// ---------------------------------------------------------------------------
__device__ __forceinline__ void cp16(uint32_t saddr, const void* g) {
    asm volatile("cp.async.cg.shared.global [%0], [%1], 16;" ::"r"(saddr), "l"(g));
}
__device__ __forceinline__ void ldsm4(uint32_t* r, uint32_t addr) {
    asm volatile("ldmatrix.sync.aligned.m8n8.x4.shared.b16 {%0,%1,%2,%3}, [%4];"
                 : "=r"(r[0]), "=r"(r[1]), "=r"(r[2]), "=r"(r[3]) : "r"(addr));
}
__device__ __forceinline__ void ldsm2(uint32_t* r, uint32_t addr) {
    asm volatile("ldmatrix.sync.aligned.m8n8.x2.shared.b16 {%0,%1}, [%2];"
                 : "=r"(r[0]), "=r"(r[1]) : "r"(addr));
}
__device__ __forceinline__ void mma_f16(float* c, const uint32_t* a, const uint32_t* b) {
    asm volatile(
        "mma.sync.aligned.m16n8k16.row.col.f32.f16.f16.f32 "
        "{%0,%1,%2,%3}, {%4,%5,%6,%7}, {%8,%9}, {%0,%1,%2,%3};"
        : "+f"(c[0]), "+f"(c[1]), "+f"(c[2]), "+f"(c[3])
        : "r"(a[0]), "r"(a[1]), "r"(a[2]), "r"(a[3]), "r"(b[0]), "r"(b[1]));
}

// ---------------------------------------------------------------------------
// GEMM: out[M,N] = Xh @ Wq^T with per-128-block fp32 scaling + bias
// ---------------------------------------------------------------------------
__global__ __launch_bounds__(THREADS, 1)
void k_gemm(const float* __restrict__ scales, const float* __restrict__ bias,
            float* __restrict__ out) {
    extern __shared__ char smc[];
    float* sscale = reinterpret_cast<float*>(smc);
    const uint32_t sbase = (uint32_t)__cvta_generic_to_shared(smc);
    const int tid  = threadIdx.x;
    const int lane = tid & 31;
    const int warp = tid >> 5;
    const long m0 = (long)blockIdx.y * BM;
    const long n0 = (long)blockIdx.x * BN;
    const int wm = (warp & 1) * 64;
    const int wn = (warp >> 1) * 32;

    // Preload scale tile transposed: sscale[kb*128 + n] = scales[(n0+n)*32 + kb]
#pragma unroll
    for (int i = tid; i < BN * 32; i += THREADS) {
        const int n = i >> 5, kb = i & 31;
        sscale[kb * 128 + n] = scales[(n0 + n) * 32 + kb];
    }

    float c[4][4][4], p[4][4][4];
#pragma unroll
    for (int mi = 0; mi < 4; ++mi)
#pragma unroll
        for (int ni = 0; ni < 4; ++ni)
#pragma unroll
            for (int j = 0; j < 4; ++j) { c[mi][ni][j] = 0.f; p[mi][ni][j] = 0.f; }

    // cp.async loader: thread t handles chunks c = t + i*256; row=c>>3, ch=c&7
    auto load_stage = [&](int kt, int s) {
        const uint32_t st = sbase + SM_TILES + s * STG_B;
        const int kc0 = kt * BK;
#pragma unroll
        for (int i = 0; i < 4; ++i) {
            const int cch = tid + i * THREADS;
            const int row = cch >> 3;
            const int ch  = cch & 7;
            const uint32_t off = (uint32_t)(row * ROWB + ch * 16);
            const long gx = (m0 + row) * K_DIM + kc0 + ch * 8;
            const long gw = (n0 + row) * (long)K_DIM + kc0 + ch * 8;
            cp16(st + off, g_xh + gx);
            cp16(st + ARR_B + off, g_wh + gw);
        }
        asm volatile("cp.async.commit_group;");
    };

    const int KT = K_DIM / BK;   // 64
    load_stage(0, 0);
    load_stage(1, 1);
    load_stage(2, 2);

    const int qr = lane >> 2;
    const int qc = (lane & 3) * 2;
    const uint32_t a_rowoff = (uint32_t)(wm + (lane & 15));
    const uint32_t a_cb     = (uint32_t)((lane >> 4) * 16);
    const uint32_t b_rowoff = (uint32_t)(wn + (lane & 7));
    const uint32_t b_cb     = (uint32_t)(((lane >> 3) & 1) * 16);

    for (int kt = 0; kt < KT; ++kt) {
        const int s = kt % STAGES;
        asm volatile("cp.async.wait_group %0;" :: "n"(STAGES - 2));
        __syncthreads();
        if (kt + 3 < KT) load_stage(kt + 3, (kt + 3) % STAGES);

        const uint32_t st = sbase + SM_TILES + s * STG_B;
#pragma unroll
        for (int kk = 0; kk < 4; ++kk) {
            uint32_t ah[4][4], bf[4][2];
#pragma unroll
            for (int mi = 0; mi < 4; ++mi) {
                const uint32_t off = (a_rowoff + mi * 16) * ROWB + kk * 32 + a_cb;
                ldsm4(ah[mi], st + off);
            }
#pragma unroll
            for (int ni = 0; ni < 4; ++ni) {
                const uint32_t off = (b_rowoff + ni * 8) * ROWB + kk * 32 + b_cb;
                ldsm2(bf[ni], st + ARR_B + off);
            }
#pragma unroll
            for (int mi = 0; mi < 4; ++mi)
#pragma unroll
                for (int ni = 0; ni < 4; ++ni)
                    mma_f16(p[mi][ni], ah[mi], bf[ni]);
        }

        // Every 2 BK iters = one 128-elem scale block: C += s * part
        if (kt & 1) {
            const int kb = kt >> 1;
            const float* sk = sscale + kb * 128;
#pragma unroll
            for (int ni = 0; ni < 4; ++ni) {
                const int col = wn + ni * 8 + qc;
                const float s0 = sk[col];
                const float s1 = sk[col + 1];
#pragma unroll
                for (int mi = 0; mi < 4; ++mi) {
                    c[mi][ni][0] += s0 * p[mi][ni][0];
                    c[mi][ni][1] += s1 * p[mi][ni][1];
                    c[mi][ni][2] += s0 * p[mi][ni][2];
                    c[mi][ni][3] += s1 * p[mi][ni][3];
                    p[mi][ni][0] = 0.f; p[mi][ni][1] = 0.f;
                    p[mi][ni][2] = 0.f; p[mi][ni][3] = 0.f;
                }
            }
        }
    }

    // Epilogue: y += bias, store
#pragma unroll
    for (int mi = 0; mi < 4; ++mi) {
        const long gm = m0 + wm + mi * 16 + qr;
        float* o0 = out + gm * N_DIM + n0 + wn;
        float* o1 = o0 + 8L * N_DIM;
#pragma unroll
        for (int ni = 0; ni < 4; ++ni) {
            const int col = (int)n0 + wn + ni * 8 + qc;
            const float b0 = __ldg(bias + col);
            const float b1 = __ldg(bias + col + 1);
            float2 v0 = make_float2(c[mi][ni][0] + b0, c[mi][ni][1] + b1);
            float2 v1 = make_float2(c[mi][ni][2] + b0, c[mi][ni][3] + b1);
            *reinterpret_cast<float2*>(o0 + ni * 8 + qc) = v0;
            *reinterpret_cast<float2*>(o1 + ni * 8 + qc) = v1;
        }
    }
}

// ---------------------------------------------------------------------------
// Launch
// ---------------------------------------------------------------------------
extern "C" void kernel_launch(void* const* d_in, const int* in_sizes, int n_in,
                              void* d_out, int out_size) {
    const float* x      = (const float*)d_in[0];
    const float* wq     = (const float*)d_in[1];
    const float* scales = (const float*)d_in[2];
    const float* bias   = (const float*)d_in[3];
    float* out = (float*)d_out;

    const long n_x = in_sizes[0];           // M*K
    const long M   = n_x / K_DIM;           // 8192
    const long n_w = (long)N_DIM * K_DIM;

    {
        long n4 = n_x / 4;
        k_prep_x<<<(int)((n4 + 255) / 256), 256>>>(x, n4);
    }
    {
        long n4 = n_w / 4;
        k_prep_w<<<(int)((n4 + 255) / 256), 256>>>(wq, n4);
    }

    cudaFuncSetAttribute(k_gemm, cudaFuncAttributeMaxDynamicSharedMemorySize,
                         SMEM_TOTAL);
    dim3 grid(N_DIM / BN, (unsigned)(M / BM));
    k_gemm<<<grid, THREADS, SMEM_TOTAL>>>(scales, bias, out);
}

// round 6
// speedup vs baseline: 3.2461x; 1.3661x over previous
#include <cuda_runtime.h>
#include <cuda_fp16.h>
#include <cstdint>

// Problem constants
#define K_DIM 4096
#define N_DIM 4096
#define M_DIM 8192

// GEMM tiling
#define BM 128
#define BN 128
#define BK 64
#define STAGES 3
#define THREADS 256

// smem layout
#define ROWB 144                    // 64 halves (128B) + 16B pad -> conflict-free ldsm
#define ARR_B (128 * ROWB)          // 18432 B per operand tile
#define STG_B (2 * ARR_B)           // x, w tiles per stage
#define SMEM_TOTAL (STAGES * STG_B) // 110592 B -> 2 CTAs/SM

// Scratch: fp16 operands. Scale folded into w at prep (adds ~2^-11 w error).
__device__ __half g_xh[(long)M_DIM * K_DIM];
__device__ __half g_wh[(long)N_DIM * K_DIM];

// ---------------------------------------------------------------------------
// Prep kernels
// ---------------------------------------------------------------------------
__global__ void k_prep_x(const float* __restrict__ x, long n4) {
    long i = (long)blockIdx.x * blockDim.x + threadIdx.x;
    if (i >= n4) return;
    float4 v = reinterpret_cast<const float4*>(x)[i];
    __half2* hi2 = reinterpret_cast<__half2*>(g_xh);
    hi2[2 * i]     = __halves2half2(__float2half_rn(v.x), __float2half_rn(v.y));
    hi2[2 * i + 1] = __halves2half2(__float2half_rn(v.z), __float2half_rn(v.w));
}

__global__ void k_prep_w(const float* __restrict__ wq,
                         const float* __restrict__ scales, long n4) {
    long i = (long)blockIdx.x * blockDim.x + threadIdx.x;
    if (i >= n4) return;
    const float s = scales[(4 * i) >> 7];   // 128-elem blocks; float4 never straddles
    float4 v = reinterpret_cast<const float4*>(wq)[i];
    __half2* w2 = reinterpret_cast<__half2*>(g_wh);
    w2[2 * i]     = __halves2half2(__float2half_rn(v.x * s), __float2half_rn(v.y * s));
    w2[2 * i + 1] = __halves2half2(__float2half_rn(v.z * s), __float2half_rn(v.w * s));
}

// ---------------------------------------------------------------------------
// MMA helpers
// ---------------------------------------------------------------------------
__device__ __forceinline__ void cp16(uint32_t saddr, const void* g) {
    asm volatile("cp.async.cg.shared.global [%0], [%1], 16;" ::"r"(saddr), "l"(g));
}
__device__ __forceinline__ void ldsm4(uint32_t* r, uint32_t addr) {
    asm volatile("ldmatrix.sync.aligned.m8n8.x4.shared.b16 {%0,%1,%2,%3}, [%4];"
                 : "=r"(r[0]), "=r"(r[1]), "=r"(r[2]), "=r"(r[3]) : "r"(addr));
}
__device__ __forceinline__ void ldsm2(uint32_t* r, uint32_t addr) {
    asm volatile("ldmatrix.sync.aligned.m8n8.x2.shared.b16 {%0,%1}, [%2];"
                 : "=r"(r[0]), "=r"(r[1]) : "r"(addr));
}
__device__ __forceinline__ void mma_f16(float* c, const uint32_t* a, const uint32_t* b) {
    asm volatile(
        "mma.sync.aligned.m16n8k16.row.col.f32.f16.f16.f32 "
        "{%0,%1,%2,%3}, {%4,%5,%6,%7}, {%8,%9}, {%0,%1,%2,%3};"
        : "+f"(c[0]), "+f"(c[1]), "+f"(c[2]), "+f"(c[3])
        : "r"(a[0]), "r"(a[1]), "r"(a[2]), "r"(a[3]), "r"(b[0]), "r"(b[1]));
}

// ---------------------------------------------------------------------------
// GEMM: out[M,N] = X16 @ W16^T + bias   (scales pre-folded into W16)
// ---------------------------------------------------------------------------
__global__ __launch_bounds__(THREADS, 2)
void k_gemm(const float* __restrict__ bias, float* __restrict__ out) {
    extern __shared__ char smc[];
    const uint32_t sbase = (uint32_t)__cvta_generic_to_shared(smc);
    const int tid  = threadIdx.x;
    const int lane = tid & 31;
    const int warp = tid >> 5;
    const long m0 = (long)blockIdx.y * BM;
    const long n0 = (long)blockIdx.x * BN;
    const int wm = (warp & 1) * 64;
    const int wn = (warp >> 1) * 32;

    float c[4][4][4];
#pragma unroll
    for (int mi = 0; mi < 4; ++mi)
#pragma unroll
        for (int ni = 0; ni < 4; ++ni)
#pragma unroll
            for (int j = 0; j < 4; ++j) c[mi][ni][j] = 0.f;

    // cp.async loader: thread t handles chunks c = t + i*256; row=c>>3, ch=c&7
    auto load_stage = [&](int kt, int s) {
        const uint32_t st = sbase + s * STG_B;
        const int kc0 = kt * BK;
#pragma unroll
        for (int i = 0; i < 4; ++i) {
            const int cch = tid + i * THREADS;
            const int row = cch >> 3;
            const int ch  = cch & 7;
            const uint32_t off = (uint32_t)(row * ROWB + ch * 16);
            cp16(st + off,         g_xh + (m0 + row) * K_DIM + kc0 + ch * 8);
            cp16(st + ARR_B + off, g_wh + (n0 + row) * (long)K_DIM + kc0 + ch * 8);
        }
        asm volatile("cp.async.commit_group;");
    };

    const int KT = K_DIM / BK;   // 64
    load_stage(0, 0);
    load_stage(1, 1);

    const uint32_t a_rowoff = (uint32_t)(wm + (lane & 15));
    const uint32_t a_cb     = (uint32_t)((lane >> 4) * 16);
    const uint32_t b_rowoff = (uint32_t)(wn + (lane & 7));
    const uint32_t b_cb     = (uint32_t)(((lane >> 3) & 1) * 16);

    for (int kt = 0; kt < KT; ++kt) {
        const int s = kt % STAGES;
        asm volatile("cp.async.wait_group %0;" :: "n"(STAGES - 2));
        __syncthreads();
        if (kt + 2 < KT) load_stage(kt + 2, (kt + 2) % STAGES);

        const uint32_t st = sbase + s * STG_B;
#pragma unroll
        for (int kk = 0; kk < 4; ++kk) {
            uint32_t ah[4][4], bf[4][2];
#pragma unroll
            for (int mi = 0; mi < 4; ++mi) {
                const uint32_t off = (a_rowoff + mi * 16) * ROWB + kk * 32 + a_cb;
                ldsm4(ah[mi], st + off);
            }
#pragma unroll
            for (int ni = 0; ni < 4; ++ni) {
                const uint32_t off = (b_rowoff + ni * 8) * ROWB + kk * 32 + b_cb;
                ldsm2(bf[ni], st + ARR_B + off);
            }
#pragma unroll
            for (int mi = 0; mi < 4; ++mi)
#pragma unroll
                for (int ni = 0; ni < 4; ++ni)
                    mma_f16(c[mi][ni], ah[mi], bf[ni]);
        }
    }

    // Epilogue: y += bias, store
    const int qr = lane >> 2;
    const int qc = (lane & 3) * 2;
#pragma unroll
    for (int mi = 0; mi < 4; ++mi) {
        const long gm = m0 + wm + mi * 16 + qr;
        float* o0 = out + gm * N_DIM + n0 + wn;
        float* o1 = o0 + 8L * N_DIM;
#pragma unroll
        for (int ni = 0; ni < 4; ++ni) {
            const int col = (int)n0 + wn + ni * 8 + qc;
            const float b0 = __ldg(bias + col);
            const float b1 = __ldg(bias + col + 1);
            float2 v0 = make_float2(c[mi][ni][0] + b0, c[mi][ni][1] + b1);
            float2 v1 = make_float2(c[mi][ni][2] + b0, c[mi][ni][3] + b1);
            *reinterpret_cast<float2*>(o0 + ni * 8 + qc) = v0;
            *reinterpret_cast<float2*>(o1 + ni * 8 + qc) = v1;
        }
    }
}

// ---------------------------------------------------------------------------
// Launch
// ---------------------------------------------------------------------------
extern "C" void kernel_launch(void* const* d_in, const int* in_sizes, int n_in,
                              void* d_out, int out_size) {
    const float* x      = (const float*)d_in[0];
    const float* wq     = (const float*)d_in[1];
    const float* scales = (const float*)d_in[2];
    const float* bias   = (const float*)d_in[3];
    float* out = (float*)d_out;

    const long n_x = in_sizes[0];           // M*K
    const long M   = n_x / K_DIM;           // 8192
    const long n_w = (long)N_DIM * K_DIM;

    {
        long n4 = n_x / 4;
        k_prep_x<<<(int)((n4 + 255) / 256), 256>>>(x, n4);
    }
    {
        long n4 = n_w / 4;
        k_prep_w<<<(int)((n4 + 255) / 256), 256>>>(wq, scales, n4);
    }

    cudaFuncSetAttribute(k_gemm, cudaFuncAttributeMaxDynamicSharedMemorySize,
                         SMEM_TOTAL);
    dim3 grid(N_DIM / BN, (unsigned)(M / BM));
    k_gemm<<<grid, THREADS, SMEM_TOTAL>>>(bias, out);
}

// round 7
// speedup vs baseline: 3.2464x; 1.0001x over previous
#include <cuda_runtime.h>
#include <cuda_fp16.h>
#include <cstdint>

// Problem constants
#define K_DIM 4096
#define N_DIM 4096
#define M_DIM 8192

// GEMM tiling: CTA 128x128x64, 4 warps of 64x64
#define BM 128
#define BN 128
#define BK 64
#define STAGES 3
#define THREADS 128

// smem layout
#define ROWB 144                    // 64 halves (128B) + 16B pad -> conflict-free ldsm
#define ARR_B (128 * ROWB)          // 18432 B per operand tile
#define STG_B (2 * ARR_B)           // x, w tiles per stage
#define SMEM_TOTAL (STAGES * STG_B) // 110592 B -> 2 CTAs/SM

// Scratch: fp16 operands. Scale folded into w at prep (adds ~2^-11 w error).
__device__ __half g_xh[(long)M_DIM * K_DIM];
__device__ __half g_wh[(long)N_DIM * K_DIM];

// ---------------------------------------------------------------------------
// Prep kernels
// ---------------------------------------------------------------------------
__global__ void k_prep_x(const float* __restrict__ x, long n4) {
    long i = (long)blockIdx.x * blockDim.x + threadIdx.x;
    if (i >= n4) return;
    float4 v = reinterpret_cast<const float4*>(x)[i];
    __half2* hi2 = reinterpret_cast<__half2*>(g_xh);
    hi2[2 * i]     = __halves2half2(__float2half_rn(v.x), __float2half_rn(v.y));
    hi2[2 * i + 1] = __halves2half2(__float2half_rn(v.z), __float2half_rn(v.w));
}

__global__ void k_prep_w(const float* __restrict__ wq,
                         const float* __restrict__ scales, long n4) {
    long i = (long)blockIdx.x * blockDim.x + threadIdx.x;
    if (i >= n4) return;
    const float s = scales[(4 * i) >> 7];   // 128-elem blocks; float4 never straddles
    float4 v = reinterpret_cast<const float4*>(wq)[i];
    __half2* w2 = reinterpret_cast<__half2*>(g_wh);
    w2[2 * i]     = __halves2half2(__float2half_rn(v.x * s), __float2half_rn(v.y * s));
    w2[2 * i + 1] = __halves2half2(__float2half_rn(v.z * s), __float2half_rn(v.w * s));
}

// ---------------------------------------------------------------------------
// MMA helpers
// ---------------------------------------------------------------------------
__device__ __forceinline__ void cp16(uint32_t saddr, const void* g) {
    asm volatile("cp.async.cg.shared.global [%0], [%1], 16;" ::"r"(saddr), "l"(g));
}
__device__ __forceinline__ void ldsm4(uint32_t* r, uint32_t addr) {
    asm volatile("ldmatrix.sync.aligned.m8n8.x4.shared.b16 {%0,%1,%2,%3}, [%4];"
                 : "=r"(r[0]), "=r"(r[1]), "=r"(r[2]), "=r"(r[3]) : "r"(addr));
}
__device__ __forceinline__ void mma_f16(float* c, const uint32_t* a, const uint32_t* b) {
    asm volatile(
        "mma.sync.aligned.m16n8k16.row.col.f32.f16.f16.f32 "
        "{%0,%1,%2,%3}, {%4,%5,%6,%7}, {%8,%9}, {%0,%1,%2,%3};"
        : "+f"(c[0]), "+f"(c[1]), "+f"(c[2]), "+f"(c[3])
        : "r"(a[0]), "r"(a[1]), "r"(a[2]), "r"(a[3]), "r"(b[0]), "r"(b[1]));
}

// ---------------------------------------------------------------------------
// GEMM: out[M,N] = X16 @ W16^T + bias   (scales pre-folded into W16)
// 4 warps, each computes a 64x64 sub-tile.
// ---------------------------------------------------------------------------
__global__ __launch_bounds__(THREADS, 2)
void k_gemm(const float* __restrict__ bias, float* __restrict__ out) {
    extern __shared__ char smc[];
    const uint32_t sbase = (uint32_t)__cvta_generic_to_shared(smc);
    const int tid  = threadIdx.x;
    const int lane = tid & 31;
    const int warp = tid >> 5;
    const long m0 = (long)blockIdx.y * BM;
    const long n0 = (long)blockIdx.x * BN;
    const int wm = (warp & 1) * 64;
    const int wn = (warp >> 1) * 64;

    float c[4][8][4];
#pragma unroll
    for (int mi = 0; mi < 4; ++mi)
#pragma unroll
        for (int ni = 0; ni < 8; ++ni)
#pragma unroll
            for (int j = 0; j < 4; ++j) c[mi][ni][j] = 0.f;

    // cp.async loader: 2048 16B-chunks per stage (2 arrays x 1024), 16/thread
    auto load_stage = [&](int kt, int s) {
        const uint32_t st = sbase + s * STG_B;
        const int kc0 = kt * BK;
#pragma unroll
        for (int i = 0; i < 8; ++i) {
            const int cch = tid + i * THREADS;
            const int row = cch >> 3;
            const int ch  = cch & 7;
            const uint32_t off = (uint32_t)(row * ROWB + ch * 16);
            cp16(st + off,         g_xh + (m0 + row) * K_DIM + kc0 + ch * 8);
            cp16(st + ARR_B + off, g_wh + (n0 + row) * (long)K_DIM + kc0 + ch * 8);
        }
        asm volatile("cp.async.commit_group;");
    };

    const int KT = K_DIM / BK;   // 64
    load_stage(0, 0);
    load_stage(1, 1);

    // A ldsm4: 16 rows x 16 cols per mi group
    const uint32_t a_rowoff = (uint32_t)(wm + (lane & 15));
    const uint32_t a_cb     = (uint32_t)((lane >> 4) * 16);      // bytes
    // B ldsm4: 16 rows (two n8 groups) x 16 cols per nj group
    const uint32_t b_rowoff = (uint32_t)(wn + (lane & 7) + ((lane >> 4) * 8));
    const uint32_t b_cb     = (uint32_t)(((lane >> 3) & 1) * 16); // bytes

    for (int kt = 0; kt < KT; ++kt) {
        const int s = kt % STAGES;
        asm volatile("cp.async.wait_group %0;" :: "n"(STAGES - 2));
        __syncthreads();
        if (kt + 2 < KT) load_stage(kt + 2, (kt + 2) % STAGES);

        const uint32_t st = sbase + s * STG_B;
#pragma unroll
        for (int kk = 0; kk < 4; ++kk) {
            uint32_t ah[4][4], bq[4][4];
#pragma unroll
            for (int mi = 0; mi < 4; ++mi) {
                const uint32_t off = (a_rowoff + mi * 16) * ROWB + kk * 32 + a_cb;
                ldsm4(ah[mi], st + off);
            }
#pragma unroll
            for (int nj = 0; nj < 4; ++nj) {
                const uint32_t off = (b_rowoff + nj * 16) * ROWB + kk * 32 + b_cb;
                ldsm4(bq[nj], st + ARR_B + off);
            }
#pragma unroll
            for (int mi = 0; mi < 4; ++mi)
#pragma unroll
                for (int nj = 0; nj < 4; ++nj) {
                    mma_f16(c[mi][2 * nj],     ah[mi], &bq[nj][0]);
                    mma_f16(c[mi][2 * nj + 1], ah[mi], &bq[nj][2]);
                }
        }
    }

    // Epilogue: y += bias, store (each warp: 64 rows x 64 cols)
    const int qr = lane >> 2;
    const int qc = (lane & 3) * 2;
#pragma unroll
    for (int mi = 0; mi < 4; ++mi) {
        const long gm = m0 + wm + mi * 16 + qr;
        float* o0 = out + gm * N_DIM + n0 + wn;
        float* o1 = o0 + 8L * N_DIM;
#pragma unroll
        for (int ni = 0; ni < 8; ++ni) {
            const int col = (int)n0 + wn + ni * 8 + qc;
            const float b0 = __ldg(bias + col);
            const float b1 = __ldg(bias + col + 1);
            float2 v0 = make_float2(c[mi][ni][0] + b0, c[mi][ni][1] + b1);
            float2 v1 = make_float2(c[mi][ni][2] + b0, c[mi][ni][3] + b1);
            *reinterpret_cast<float2*>(o0 + ni * 8 + qc) = v0;
            *reinterpret_cast<float2*>(o1 + ni * 8 + qc) = v1;
        }
    }
}

// ---------------------------------------------------------------------------
// Launch
// ---------------------------------------------------------------------------
extern "C" void kernel_launch(void* const* d_in, const int* in_sizes, int n_in,
                              void* d_out, int out_size) {
    const float* x      = (const float*)d_in[0];
    const float* wq     = (const float*)d_in[1];
    const float* scales = (const float*)d_in[2];
    const float* bias   = (const float*)d_in[3];
    float* out = (float*)d_out;

    const long n_x = in_sizes[0];           // M*K
    const long M   = n_x / K_DIM;           // 8192
    const long n_w = (long)N_DIM * K_DIM;

    {
        long n4 = n_x / 4;
        k_prep_x<<<(int)((n4 + 255) / 256), 256>>>(x, n4);
    }
    {
        long n4 = n_w / 4;
        k_prep_w<<<(int)((n4 + 255) / 256), 256>>>(wq, scales, n4);
    }

    cudaFuncSetAttribute(k_gemm, cudaFuncAttributeMaxDynamicSharedMemorySize,
                         SMEM_TOTAL);
    dim3 grid(N_DIM / BN, (unsigned)(M / BM));
    k_gemm<<<grid, THREADS, SMEM_TOTAL>>>(bias, out);
}